// round 13
// baseline (speedup 1.0000x reference)
#include <cuda_runtime.h>
#include <cuda_fp16.h>
#include <math.h>

#define Bd 2
#define Td 2048
#define Hd 1024
#define Ld 256
#define Fd 2048
#define Ed 7
#define BTd (Bd*Td)

// weight fp16 pool offsets (in halves)
#define W_QPD 0
#define W_KVD 262144
#define W_VPU 524288
#define W_RQ  786432
#define W_RK  1048576
#define W_OPJ 2097152
#define W_SHG 3145728
#define W_SHU 5242880
#define W_SHD 7340032
#define W_EXG 9437184
#define W_EXU 24117248
#define W_EXD 38797312
#define W_TOT 53477376

#define SMEM_BYTES 98304   // 4 stages x (A 8KB + B 16KB)

// ---------------- scratch (device globals; no allocation) ----------------
__device__ __half g_w16[W_TOT];
__device__ __half g_h16[BTd*Hd];
__device__ __half g_qlat16[BTd*Ld];
__device__ __half g_kvlat16[BTd*Ld];
__device__ __half g_vT16[BTd*Hd];      // [Bd][Hd][Td]
__device__ __half g_q16[BTd*Hd];
__device__ __half g_k16[BTd*Hd];
__device__ __half g_sc16[(size_t)Bd*Td*Td];
__device__ __half g_y16[BTd*Hd];
__device__ __half g_h2_16[BTd*Hd];
__device__ __half g_gbuf16[(size_t)8*BTd*Fd];  // 7 routed + 1 shared slices
__device__ float  g_h2[BTd*Hd];
__device__ float  g_x1[BTd*Hd];
__device__ float  g_shb[BTd*Hd];
__device__ float  g_r0[BTd*Hd];
__device__ float  g_r1[BTd*Hd];
__device__ int    g_cnt[Ed];
__device__ int    g_gidx[Ed*BTd];
__device__ float  g_gwt[Ed*BTd];
__device__ int    g_gslot[Ed*BTd];

// ---------------- fp16 helpers ----------------
__device__ __forceinline__ unsigned f2h2(float lo, float hi) {
    __half2 h = __floats2half2_rn(lo, hi);
    return *(unsigned*)&h;
}

// ---------------- weight conversion ----------------
struct CVT {
    const float* src[12];
    __half* dst[12];
    int n[12];
};

__global__ void cvt_kernel(CVT cv) {
    int seg = blockIdx.y;
    int idx = blockIdx.x * 256 + threadIdx.x;
    int n8 = cv.n[seg] >> 3;
    if (idx >= n8) return;
    const float4* s = (const float4*)cv.src[seg];
    float4 f1 = s[2*idx], f2 = s[2*idx+1];
    uint4 o;
    o.x = f2h2(f1.x, f1.y); o.y = f2h2(f1.z, f1.w);
    o.z = f2h2(f2.x, f2.y); o.w = f2h2(f2.z, f2.w);
    ((uint4*)cv.dst[seg])[idx] = o;
}

// ---------------- block reduce ----------------
template<bool DOMAX>
__device__ __forceinline__ float blockReduce(float v) {
    __shared__ float sh[8];
    __shared__ float res;
    int lane = threadIdx.x & 31, w = threadIdx.x >> 5;
    #pragma unroll
    for (int o = 16; o; o >>= 1) {
        float t = __shfl_xor_sync(0xffffffffu, v, o);
        v = DOMAX ? fmaxf(v, t) : v + t;
    }
    if (lane == 0) sh[w] = v;
    __syncthreads();
    if (w == 0) {
        v = (lane < (int)(blockDim.x >> 5)) ? sh[lane] : (DOMAX ? -3.4e38f : 0.f);
        #pragma unroll
        for (int o = 4; o; o >>= 1) {
            float t = __shfl_xor_sync(0xffffffffu, v, o);
            v = DOMAX ? fmaxf(v, t) : v + t;
        }
        if (lane == 0) res = v;
    }
    __syncthreads();
    return res;
}

// ---------------- layernorm (fp16 out, optional fp32 copy) ----------------
__global__ void ln_kernel(const float* __restrict__ x, const float* __restrict__ w,
                          __half* __restrict__ o16, float* __restrict__ o32) {
    int row = blockIdx.x;
    const float* xr = x + (size_t)row * Hd;
    int t = threadIdx.x;
    float v[4];
    float s = 0.f;
    #pragma unroll
    for (int i = 0; i < 4; i++) { v[i] = xr[t + 256*i]; s += v[i]; }
    s = blockReduce<false>(s);
    float mu = s * (1.f / Hd);
    float q = 0.f;
    #pragma unroll
    for (int i = 0; i < 4; i++) { float d = v[i] - mu; q += d * d; }
    q = blockReduce<false>(q);
    float rs = rsqrtf(q * (1.f / Hd) + 1e-5f);
    #pragma unroll
    for (int i = 0; i < 4; i++) {
        float val = (v[i] - mu) * rs * w[t + 256*i];
        o16[(size_t)row*Hd + t + 256*i] = __float2half_rn(val);
        if (o32) o32[(size_t)row*Hd + t + 256*i] = val;
    }
}

// ---------------- rope (fp16 in/out) ----------------
__global__ void rope_kernel(__half* __restrict__ q, __half* __restrict__ k) {
    int row = blockIdx.x;
    int t = row % Td;
    size_t base = (size_t)row * Hd;
    #pragma unroll
    for (int it = 0; it < 2; it++) {
        int p = threadIdx.x + 256 * it;
        double invf = exp(-(double)(2 * p) / 1024.0 * 9.210340371976184);
        float f = (float)t * (float)invf;
        float c = cosf(f), s = sinf(f);
        float q1 = __half2float(q[base + p]), q2 = __half2float(q[base + p + 512]);
        q[base + p]       = __float2half_rn(q1 * c - q2 * s);
        q[base + p + 512] = __float2half_rn(q2 * c + q1 * s);
        float k1 = __half2float(k[base + p]), k2 = __half2float(k[base + p + 512]);
        k[base + p]       = __float2half_rn(k1 * c - k2 * s);
        k[base + p + 512] = __float2half_rn(k2 * c + k1 * s);
    }
}

// ---------------- softmax (causal, fp16, single pass) ----------------
__global__ void softmax_kernel(__half* __restrict__ sc) {
    int b = blockIdx.y, i = blockIdx.x;
    __half* row = sc + ((size_t)b * Td + i) * Td;
    int t = threadIdx.x;
    int n = i + 1;
    uint4 u = *(const uint4*)(row + t*8);
    __half2* hp = (__half2*)&u;
    float v[8];
    #pragma unroll
    for (int j = 0; j < 4; j++) {
        v[2*j]   = __low2float(hp[j]);
        v[2*j+1] = __high2float(hp[j]);
    }
    float mx = -3.4e38f;
    #pragma unroll
    for (int j = 0; j < 8; j++)
        if (t*8 + j < n) mx = fmaxf(mx, v[j]);
    mx = blockReduce<true>(mx);
    float s = 0.f;
    #pragma unroll
    for (int j = 0; j < 8; j++) {
        float e = (t*8 + j < n) ? expf(v[j] - mx) : 0.f;
        v[j] = e; s += e;
    }
    s = blockReduce<false>(s);
    float inv = 1.f / s;
    #pragma unroll
    for (int j = 0; j < 4; j++)
        hp[j] = __floats2half2_rn(v[2*j]*inv, v[2*j+1]*inv);
    *(uint4*)(row + t*8) = u;
}

// ---------------- router + top2 gather lists ----------------
__global__ void zero_cnt_kernel() {
    if (threadIdx.x < Ed) g_cnt[threadIdx.x] = 0;
}

__global__ void router_kernel(const float* __restrict__ h2, const float* __restrict__ rw,
                              const float* __restrict__ rb) {
    int m = blockIdx.x;
    int w = threadIdx.x >> 5, lane = threadIdx.x & 31;
    __shared__ float probs[Ed];
    if (w < Ed) {
        const float* hv = h2 + (size_t)m * Hd;
        const float* wv = rw + (size_t)w * Hd;
        float s = 0.f;
        for (int j = lane; j < Hd; j += 32) s += hv[j] * wv[j];
        #pragma unroll
        for (int o = 16; o; o >>= 1) s += __shfl_xor_sync(0xffffffffu, s, o);
        if (lane == 0) probs[w] = 1.f / (1.f + expf(-(s + rb[w])));
    }
    __syncthreads();
    if (threadIdx.x == 0) {
        int e0 = 0; float p0 = probs[0];
        for (int e = 1; e < Ed; e++) if (probs[e] > p0) { p0 = probs[e]; e0 = e; }
        int e1 = -1; float p1 = -3.4e38f;
        for (int e = 0; e < Ed; e++) if (e != e0 && probs[e] > p1) { p1 = probs[e]; e1 = e; }
        int pos = atomicAdd(&g_cnt[e0], 1);
        g_gidx[e0*BTd + pos] = m; g_gwt[e0*BTd + pos] = p0; g_gslot[e0*BTd + pos] = 0;
        pos = atomicAdd(&g_cnt[e1], 1);
        g_gidx[e1*BTd + pos] = m; g_gwt[e1*BTd + pos] = p1; g_gslot[e1*BTd + pos] = 1;
    }
}

// ---------------- mma / ldmatrix / cp.async ----------------
__device__ __forceinline__ void mma_f16(float* d, const unsigned* a, const unsigned* b) {
    asm volatile(
        "mma.sync.aligned.m16n8k16.row.col.f32.f16.f16.f32 "
        "{%0,%1,%2,%3}, {%4,%5,%6,%7}, {%8,%9}, {%0,%1,%2,%3};"
        : "+f"(d[0]), "+f"(d[1]), "+f"(d[2]), "+f"(d[3])
        : "r"(a[0]), "r"(a[1]), "r"(a[2]), "r"(a[3]), "r"(b[0]), "r"(b[1]));
}

__device__ __forceinline__ void ldsm4(unsigned* r, unsigned addr) {
    asm volatile("ldmatrix.sync.aligned.m8n8.x4.shared.b16 {%0,%1,%2,%3}, [%4];"
        : "=r"(r[0]), "=r"(r[1]), "=r"(r[2]), "=r"(r[3]) : "r"(addr));
}

__device__ __forceinline__ void cpa16(unsigned dst, const void* src, unsigned sz) {
    asm volatile("cp.async.cg.shared.global [%0], [%1], 16, %2;"
        :: "r"(dst), "l"(src), "r"(sz) : "memory");
}

__device__ __forceinline__ unsigned smem_u32(const void* p) {
    unsigned a;
    asm("{ .reg .u64 t; cvta.to.shared.u64 t, %1; cvt.u32.u64 %0, t; }" : "=r"(a) : "l"(p));
    return a;
}

// crosswise swizzle: 16B chunk (row, c) -> byte offset within a tile buffer
__device__ __forceinline__ unsigned swz(int row, int c) {
    int line = row >> 1;
    return (unsigned)(line*128 + (((((row & 1) << 2) | c) ^ (line & 7)) << 4));
}

// per-z dims + pointer tables for heterogeneous batched launches
struct GA {
    const void* A[8];
    const void* B[8];
    void*       C[8];
    const void* aux[8];
    float* r0; float* r1;
    int M[8], N[8], K[8], lda[8], ldb[8], ldc[8];
    int ngather;   // z < ngather -> A rows gathered via gidx, Meff = gcnt[z]
    const int* gcnt; const int* gidx; const float* gwt; const int* gslot;
};

// ---------------- fp16 mma GEMM, 128x256 tile, 512 thr, cp.async 4-stage --
// C = A @ B^T, per-z shapes. 16 warps, 4x4 grid, warp tile 32x64.
// All 12 ldmatrix of both k16 sub-steps are issued before the 32 mma so the
// LSU phase overlaps the tensor phase (scoreboard releases mma(g0) after the
// first 6 ldsm while g1's ldsm are still in flight).
// MODE 0: C=v  1: silu  2: C=v*aux  3: C=v+aux(f32)
//      4: scatter w*v to (r0|r1)[gidx] (f32)   5: C=v/32, causal tile skip
// KLIM: clamp K to bm+128 (causal PV)
template<int MODE, bool OHALF, bool KLIM>
__global__ void __launch_bounds__(512) gemm8(GA ga) {
    const int z = blockIdx.z;
    const int bm = blockIdx.y * 128;
    const int bn = blockIdx.x * 256;
    const int Mz = ga.M[z], Nz = ga.N[z];
    if (bn >= Nz || bm >= Mz) return;
    if (MODE == 5 && bn > bm + 127) return;

    const bool gath = z < ga.ngather;
    int Meff = Mz;
    const int* gidx = nullptr; const float* gwt = nullptr; const int* gslot = nullptr;
    if (gath || MODE == 4) {
        Meff = ga.gcnt[z];
        gidx = ga.gidx + z * BTd;
        gwt  = ga.gwt  + z * BTd;
        gslot= ga.gslot+ z * BTd;
    }
    if (bm >= Meff) return;

    const __half* __restrict__ A  = (const __half*)ga.A[z];
    const __half* __restrict__ Bm = (const __half*)ga.B[z];
    int K = ga.K[z];
    if (KLIM) K = (bm + 128 < K) ? bm + 128 : K;
    const int lda = ga.lda[z], ldb = ga.ldb[z], ldc = ga.ldc[z];

    extern __shared__ __align__(16) unsigned char smraw[];
    const unsigned sbase = smem_u32(smraw);

    const int tid = threadIdx.x;
    const int lane = tid & 31, wid = tid >> 5;
    const int wm = wid & 3, wn = wid >> 2;      // 4 x 4 warps, 32x64 each
    const int gid = lane >> 2, tig = lane & 3;

    // ---- cp.async source setup ----
    const int tid4 = tid >> 2, cA = tid & 3;
    const __half* srcA; unsigned szA; unsigned dA;
    {
        int lr = tid4;
        int gr = bm + lr;
        bool val = gr < Meff;
        int sr = val ? (gath ? gidx[gr] : gr) : 0;
        srcA = A + (size_t)sr * lda + cA * 8;
        szA = val ? 16u : 0u;
        dA = swz(lr, cA);
    }
    const __half* srcB[2]; unsigned dB[2]; unsigned szB[2];
    #pragma unroll
    for (int j = 0; j < 2; j++) {
        int lr = tid4 + 128*j;
        int gr = bn + lr;
        bool val = gr < Nz;
        srcB[j] = Bm + (size_t)(val ? gr : 0) * ldb + cA * 8;
        szB[j] = val ? 16u : 0u;
        dB[j] = swz(lr, cA);
    }

    // ---- ldmatrix per-lane offsets (stage-relative) ----
    unsigned offA[2][2], offB[4][2];
    #pragma unroll
    for (int mt = 0; mt < 2; mt++) {
        int row = wm*32 + mt*16 + ((lane >> 3) & 1)*8 + (lane & 7);
        #pragma unroll
        for (int g = 0; g < 2; g++)
            offA[mt][g] = swz(row, g*2 + ((lane >> 4) & 1));
    }
    #pragma unroll
    for (int q = 0; q < 4; q++) {
        int row = wn*64 + q*16 + ((lane >> 4) & 1)*8 + (lane & 7);
        #pragma unroll
        for (int g = 0; g < 2; g++)
            offB[q][g] = swz(row, g*2 + ((lane >> 3) & 1));
    }

    float acc[2][8][4];
    #pragma unroll
    for (int i = 0; i < 2; i++)
        #pragma unroll
        for (int j = 0; j < 8; j++)
            #pragma unroll
            for (int l = 0; l < 4; l++) acc[i][j][l] = 0.f;

    auto issue = [&](int it) {
        int s = it & 3;
        unsigned ab = sbase + s*24576;
        unsigned bb = ab + 8192;
        size_t ko = (size_t)it * 32;
        cpa16(ab + dA, srcA + ko, szA);
        cpa16(bb + dB[0], srcB[0] + ko, szB[0]);
        cpa16(bb + dB[1], srcB[1] + ko, szB[1]);
    };

    const int NT = K / 32;
    issue(0); asm volatile("cp.async.commit_group;" ::: "memory");
    issue(1); asm volatile("cp.async.commit_group;" ::: "memory");
    issue(2); asm volatile("cp.async.commit_group;" ::: "memory");

    for (int it = 0; it < NT; it++) {
        asm volatile("cp.async.wait_group 2;" ::: "memory");
        __syncthreads();
        if (it + 3 < NT) issue(it + 3);
        asm volatile("cp.async.commit_group;" ::: "memory");

        unsigned ab = sbase + (it & 3)*24576;
        unsigned bb = ab + 8192;
        // issue ALL ldsm of both sub-steps up front, then all mma:
        // mma(g0) depends only on the first 6 ldsm, so the tensor pipe starts
        // while the LSU drains g1's fragment loads.
        unsigned a0[2][4], b0[4][4], a1[2][4], b1[4][4];
        #pragma unroll
        for (int mt = 0; mt < 2; mt++) ldsm4(a0[mt], ab + offA[mt][0]);
        #pragma unroll
        for (int q = 0; q < 4; q++) ldsm4(b0[q], bb + offB[q][0]);
        #pragma unroll
        for (int mt = 0; mt < 2; mt++) ldsm4(a1[mt], ab + offA[mt][1]);
        #pragma unroll
        for (int q = 0; q < 4; q++) ldsm4(b1[q], bb + offB[q][1]);
        #pragma unroll
        for (int mt = 0; mt < 2; mt++)
            #pragma unroll
            for (int nt = 0; nt < 8; nt++)
                mma_f16(acc[mt][nt], a0[mt], &b0[nt >> 1][(nt & 1)*2]);
        #pragma unroll
        for (int mt = 0; mt < 2; mt++)
            #pragma unroll
            for (int nt = 0; nt < 8; nt++)
                mma_f16(acc[mt][nt], a1[mt], &b1[nt >> 1][(nt & 1)*2]);
    }

    // ---- epilogue ----
    #pragma unroll
    for (int mt = 0; mt < 2; mt++) {
        #pragma unroll
        for (int i2 = 0; i2 < 2; i2++) {
            int gm = bm + wm*32 + mt*16 + gid + i2*8;
            if (gm >= Meff) continue;
            int trow = 0; float wgt = 0.f; float* Ct = nullptr;
            if (MODE == 4) { trow = gidx[gm]; wgt = gwt[gm]; Ct = gslot[gm] ? ga.r1 : ga.r0; }
            #pragma unroll
            for (int nt = 0; nt < 8; nt++) {
                int gn = bn + wn*64 + nt*8 + tig*2;
                if (gn >= Nz) continue;
                float v0 = acc[mt][nt][i2*2 + 0];
                float v1 = acc[mt][nt][i2*2 + 1];
                size_t o = (size_t)gm * ldc + gn;
                if (MODE == 1) {
                    v0 = v0 / (1.f + expf(-v0));
                    v1 = v1 / (1.f + expf(-v1));
                } else if (MODE == 2) {
                    __half2 a2 = *(const __half2*)((const __half*)ga.aux[z] + o);
                    v0 *= __low2float(a2); v1 *= __high2float(a2);
                } else if (MODE == 3) {
                    float2 a2 = *(const float2*)((const float*)ga.aux[z] + o);
                    v0 += a2.x; v1 += a2.y;
                } else if (MODE == 5) {
                    v0 *= 0.03125f; v1 *= 0.03125f;
                }
                if (MODE == 4) {
                    float2 w2; w2.x = wgt*v0; w2.y = wgt*v1;
                    *(float2*)(Ct + (size_t)trow * ldc + gn) = w2;
                } else if (OHALF) {
                    *(__half2*)((__half*)ga.C[z] + o) = __floats2half2_rn(v0, v1);
                } else {
                    float2 w2; w2.x = v0; w2.y = v1;
                    *(float2*)((float*)ga.C[z] + o) = w2;
                }
            }
        }
    }
}

// ---------------- final add ----------------
__global__ void final_add_kernel(const float* __restrict__ a, const float* __restrict__ b,
                                 const float* __restrict__ c, const float* __restrict__ d,
                                 float* __restrict__ out) {
    size_t i = (size_t)blockIdx.x * blockDim.x + threadIdx.x;
    out[i] = a[i] + b[i] + c[i] + d[i];
}

// ---------------- launch ----------------
extern "C" void kernel_launch(void* const* d_in, const int* in_sizes, int n_in,
                              void* d_out, int out_size) {
    (void)in_sizes; (void)n_in; (void)out_size;
    const float* x         = (const float*)d_in[0];
    const float* ln1w      = (const float*)d_in[1];
    const float* ln2w      = (const float*)d_in[2];
    const float* kv_proj_d = (const float*)d_in[3];
    const float* q_proj_d  = (const float*)d_in[4];
    const float* v_proj_u  = (const float*)d_in[7];
    const float* rope_k    = (const float*)d_in[8];
    const float* rope_q    = (const float*)d_in[9];
    const float* o_proj    = (const float*)d_in[10];
    const float* router_w  = (const float*)d_in[11];
    const float* router_b  = (const float*)d_in[12];
    const float* sh_gate   = (const float*)d_in[13];
    const float* sh_up     = (const float*)d_in[14];
    const float* sh_down   = (const float*)d_in[15];
    const float* ex_gate   = (const float*)d_in[16];
    const float* ex_up     = (const float*)d_in[17];
    const float* ex_down   = (const float*)d_in[18];
    float* out = (float*)d_out;

    __half *w16,*h16,*qlat16,*kvlat16,*vT16,*q16,*k16,*sc16,*y16,*h2_16,*gbuf16;
    float *h2,*x1,*shb,*r0,*r1,*gwt;
    int *cnt,*gidx,*gslot;
    cudaGetSymbolAddress((void**)&w16, g_w16);
    cudaGetSymbolAddress((void**)&h16, g_h16);
    cudaGetSymbolAddress((void**)&qlat16, g_qlat16);
    cudaGetSymbolAddress((void**)&kvlat16, g_kvlat16);
    cudaGetSymbolAddress((void**)&vT16, g_vT16);
    cudaGetSymbolAddress((void**)&q16, g_q16);
    cudaGetSymbolAddress((void**)&k16, g_k16);
    cudaGetSymbolAddress((void**)&sc16, g_sc16);
    cudaGetSymbolAddress((void**)&y16, g_y16);
    cudaGetSymbolAddress((void**)&h2_16, g_h2_16);
    cudaGetSymbolAddress((void**)&gbuf16, g_gbuf16);
    cudaGetSymbolAddress((void**)&h2, g_h2);
    cudaGetSymbolAddress((void**)&x1, g_x1);
    cudaGetSymbolAddress((void**)&shb, g_shb);
    cudaGetSymbolAddress((void**)&r0, g_r0);
    cudaGetSymbolAddress((void**)&r1, g_r1);
    cudaGetSymbolAddress((void**)&cnt, g_cnt);
    cudaGetSymbolAddress((void**)&gidx, g_gidx);
    cudaGetSymbolAddress((void**)&gwt, g_gwt);
    cudaGetSymbolAddress((void**)&gslot, g_gslot);

    const size_t ESL = (size_t)BTd * Fd;   // per-expert gbuf16 slice

    // raise dynamic smem limit (idempotent)
    cudaFuncSetAttribute(gemm8<0,true,false>,  cudaFuncAttributeMaxDynamicSharedMemorySize, SMEM_BYTES);
    cudaFuncSetAttribute(gemm8<0,true,true>,   cudaFuncAttributeMaxDynamicSharedMemorySize, SMEM_BYTES);
    cudaFuncSetAttribute(gemm8<5,true,false>,  cudaFuncAttributeMaxDynamicSharedMemorySize, SMEM_BYTES);
    cudaFuncSetAttribute(gemm8<3,false,false>, cudaFuncAttributeMaxDynamicSharedMemorySize, SMEM_BYTES);
    cudaFuncSetAttribute(gemm8<1,true,false>,  cudaFuncAttributeMaxDynamicSharedMemorySize, SMEM_BYTES);
    cudaFuncSetAttribute(gemm8<2,true,false>,  cudaFuncAttributeMaxDynamicSharedMemorySize, SMEM_BYTES);
    cudaFuncSetAttribute(gemm8<0,false,false>, cudaFuncAttributeMaxDynamicSharedMemorySize, SMEM_BYTES);
    cudaFuncSetAttribute(gemm8<4,false,false>, cudaFuncAttributeMaxDynamicSharedMemorySize, SMEM_BYTES);

    // ---- weight conversion (fp32 -> fp16 pool) ----
    {
        CVT cv;
        cv.src[0] = q_proj_d;  cv.dst[0] = w16 + W_QPD; cv.n[0] = Ld*Hd;
        cv.src[1] = kv_proj_d; cv.dst[1] = w16 + W_KVD; cv.n[1] = Ld*Hd;
        cv.src[2] = v_proj_u;  cv.dst[2] = w16 + W_VPU; cv.n[2] = Hd*Ld;
        cv.src[3] = rope_q;    cv.dst[3] = w16 + W_RQ;  cv.n[3] = Hd*Ld;
        cv.src[4] = rope_k;    cv.dst[4] = w16 + W_RK;  cv.n[4] = Hd*Hd;
        cv.src[5] = o_proj;    cv.dst[5] = w16 + W_OPJ; cv.n[5] = Hd*Hd;
        cv.src[6] = sh_gate;   cv.dst[6] = w16 + W_SHG; cv.n[6] = Fd*Hd;
        cv.src[7] = sh_up;     cv.dst[7] = w16 + W_SHU; cv.n[7] = Fd*Hd;
        cv.src[8] = sh_down;   cv.dst[8] = w16 + W_SHD; cv.n[8] = Hd*Fd;
        cv.src[9] = ex_gate;   cv.dst[9] = w16 + W_EXG; cv.n[9] = Ed*Fd*Hd;
        cv.src[10]= ex_up;     cv.dst[10]= w16 + W_EXU; cv.n[10]= Ed*Fd*Hd;
        cv.src[11]= ex_down;   cv.dst[11]= w16 + W_EXD; cv.n[11]= Ed*Hd*Fd;
        int mx = Ed*Fd*Hd/8;
        cvt_kernel<<<dim3((mx + 255)/256, 12), 256>>>(cv);
    }

    zero_cnt_kernel<<<1, 32>>>();
    ln_kernel<<<BTd, 256>>>(x, ln1w, h16, nullptr);

    // merged: qlat (z0), kvlat (z1), k_r (z2)
    {
        GA ga = {};
        ga.A[0] = h16; ga.A[1] = h16; ga.A[2] = h16;
        ga.B[0] = w16 + W_QPD; ga.B[1] = w16 + W_KVD; ga.B[2] = w16 + W_RK;
        ga.C[0] = qlat16; ga.C[1] = kvlat16; ga.C[2] = k16;
        for (int zz = 0; zz < 3; zz++) {
            ga.M[zz] = BTd; ga.K[zz] = Hd; ga.lda[zz] = Hd; ga.ldb[zz] = Hd;
        }
        ga.N[0] = Ld; ga.N[1] = Ld; ga.N[2] = Hd;
        ga.ldc[0] = Ld; ga.ldc[1] = Ld; ga.ldc[2] = Hd;
        gemm8<0,true,false><<<dim3(Hd/256, BTd/128, 3), 512, SMEM_BYTES>>>(ga);
    }
    // merged: vT b0 (z0), vT b1 (z1), q_r (z2)
    {
        GA ga = {};
        for (int b = 0; b < Bd; b++) {
            ga.A[b] = w16 + W_VPU;
            ga.B[b] = kvlat16 + (size_t)b*Td*Ld;
            ga.C[b] = vT16 + (size_t)b*Hd*Td;
            ga.M[b] = Hd; ga.N[b] = Td; ga.K[b] = Ld;
            ga.lda[b] = Ld; ga.ldb[b] = Ld; ga.ldc[b] = Td;
        }
        ga.A[2] = qlat16; ga.B[2] = w16 + W_RQ; ga.C[2] = q16;
        ga.M[2] = BTd; ga.N[2] = Hd; ga.K[2] = Ld;
        ga.lda[2] = Ld; ga.ldb[2] = Ld; ga.ldc[2] = Hd;
        gemm8<0,true,false><<<dim3(Td/256, BTd/128, 3), 512, SMEM_BYTES>>>(ga);
    }

    rope_kernel<<<BTd, 256>>>(q16, k16);

    // scores (z=2, causal tile skip)
    {
        GA ga = {};
        for (int b = 0; b < Bd; b++) {
            ga.A[b] = q16 + (size_t)b*Td*Hd;
            ga.B[b] = k16 + (size_t)b*Td*Hd;
            ga.C[b] = sc16 + (size_t)b*Td*Td;
            ga.M[b] = Td; ga.N[b] = Td; ga.K[b] = Hd;
            ga.lda[b] = Hd; ga.ldb[b] = Hd; ga.ldc[b] = Td;
        }
        gemm8<5,true,false><<<dim3(Td/256, Td/128, Bd), 512, SMEM_BYTES>>>(ga);
    }
    softmax_kernel<<<dim3(Td, Bd), 256>>>(sc16);
    // PV (z=2): y[b] = attn[b] @ vT[b]^T, causal K-limit
    {
        GA ga = {};
        for (int b = 0; b < Bd; b++) {
            ga.A[b] = sc16 + (size_t)b*Td*Td;
            ga.B[b] = vT16 + (size_t)b*Hd*Td;
            ga.C[b] = y16 + (size_t)b*Td*Hd;
            ga.M[b] = Td; ga.N[b] = Hd; ga.K[b] = Td;
            ga.lda[b] = Td; ga.ldb[b] = Td; ga.ldc[b] = Hd;
        }
        gemm8<0,true,true><<<dim3(Hd/256, Td/128, Bd), 512, SMEM_BYTES>>>(ga);
    }
    // x1 = x + y @ o_proj.T  (fp32 out)
    {
        GA ga = {};
        ga.A[0] = y16; ga.B[0] = w16 + W_OPJ; ga.C[0] = x1; ga.aux[0] = x;
        ga.M[0] = BTd; ga.N[0] = Hd; ga.K[0] = Hd;
        ga.lda[0] = Hd; ga.ldb[0] = Hd; ga.ldc[0] = Hd;
        gemm8<3,false,false><<<dim3(Hd/256, BTd/128, 1), 512, SMEM_BYTES>>>(ga);
    }

    // ---- MoE ----
    ln_kernel<<<BTd, 256>>>(x1, ln2w, h2_16, h2);
    router_kernel<<<BTd, 256>>>(h2, router_w, router_b);

    __half* shg = gbuf16 + (size_t)7 * ESL;
    // merged gate (silu): z0..6 routed experts (gathered), z7 shared (dense)
    {
        GA ga = {};
        for (int e = 0; e < Ed; e++) {
            ga.A[e] = h2_16;
            ga.B[e] = w16 + W_EXG + (size_t)e * Fd * Hd;
            ga.C[e] = gbuf16 + (size_t)e * ESL;
        }
        ga.A[7] = h2_16; ga.B[7] = w16 + W_SHG; ga.C[7] = shg;
        for (int zz = 0; zz < 8; zz++) {
            ga.M[zz] = BTd; ga.N[zz] = Fd; ga.K[zz] = Hd;
            ga.lda[zz] = Hd; ga.ldb[zz] = Hd; ga.ldc[zz] = Fd;
        }
        ga.ngather = Ed;
        ga.gcnt = cnt; ga.gidx = gidx; ga.gwt = gwt; ga.gslot = gslot;
        gemm8<1,true,false><<<dim3(Fd/256, BTd/128, 8), 512, SMEM_BYTES>>>(ga);
    }
    // merged up (in-place multiply): z0..6 routed (gathered), z7 shared
    {
        GA ga = {};
        for (int e = 0; e < Ed; e++) {
            ga.A[e] = h2_16;
            ga.B[e] = w16 + W_EXU + (size_t)e * Fd * Hd;
            ga.C[e] = gbuf16 + (size_t)e * ESL;
            ga.aux[e] = gbuf16 + (size_t)e * ESL;
        }
        ga.A[7] = h2_16; ga.B[7] = w16 + W_SHU; ga.C[7] = shg; ga.aux[7] = shg;
        for (int zz = 0; zz < 8; zz++) {
            ga.M[zz] = BTd; ga.N[zz] = Fd; ga.K[zz] = Hd;
            ga.lda[zz] = Hd; ga.ldb[zz] = Hd; ga.ldc[zz] = Fd;
        }
        ga.ngather = Ed;
        ga.gcnt = cnt; ga.gidx = gidx; ga.gwt = gwt; ga.gslot = gslot;
        gemm8<2,true,false><<<dim3(Fd/256, BTd/128, 8), 512, SMEM_BYTES>>>(ga);
    }
    // shared down (fp32 out)
    {
        GA ga = {};
        ga.A[0] = shg; ga.B[0] = w16 + W_SHD; ga.C[0] = shb;
        ga.M[0] = BTd; ga.N[0] = Hd; ga.K[0] = Fd;
        ga.lda[0] = Fd; ga.ldb[0] = Fd; ga.ldc[0] = Hd;
        gemm8<0,false,false><<<dim3(Hd/256, BTd/128, 1), 512, SMEM_BYTES>>>(ga);
    }
    // expert down (scatter), z0..6
    {
        GA ga = {};
        for (int e = 0; e < Ed; e++) {
            ga.A[e] = gbuf16 + (size_t)e * ESL;
            ga.B[e] = w16 + W_EXD + (size_t)e * Hd * Fd;
            ga.M[e] = BTd; ga.N[e] = Hd; ga.K[e] = Fd;
            ga.lda[e] = Fd; ga.ldb[e] = Fd; ga.ldc[e] = Hd;
        }
        ga.r0 = r0; ga.r1 = r1;
        ga.ngather = 0;
        ga.gcnt = cnt; ga.gidx = gidx; ga.gwt = gwt; ga.gslot = gslot;
        gemm8<4,false,false><<<dim3(Hd/256, BTd/128, Ed), 512, SMEM_BYTES>>>(ga);
    }

    final_add_kernel<<<(BTd * Hd) / 256, 256>>>(x1, shb, r0, r1, out);
}

// round 14
// speedup vs baseline: 1.2387x; 1.2387x over previous
#include <cuda_runtime.h>
#include <cuda_fp16.h>
#include <math.h>

#define Bd 2
#define Td 2048
#define Hd 1024
#define Ld 256
#define Fd 2048
#define Ed 7
#define BTd (Bd*Td)

// weight fp16 pool offsets (in halves)
#define W_QPD 0
#define W_KVD 262144
#define W_VPU 524288
#define W_RQ  786432
#define W_RK  1048576
#define W_OPJ 2097152
#define W_SHG 3145728
#define W_SHU 5242880
#define W_SHD 7340032
#define W_EXG 9437184
#define W_EXU 24117248
#define W_EXD 38797312
#define W_TOT 53477376

#define SMEM_BYTES 65536   // 4 stages x (A 8KB + B 8KB)

// ---------------- scratch (device globals; no allocation) ----------------
__device__ __half g_w16[W_TOT];
__device__ __half g_h16[BTd*Hd];
__device__ __half g_qlat16[BTd*Ld];
__device__ __half g_kvlat16[BTd*Ld];
__device__ __half g_vT16[BTd*Hd];      // [Bd][Hd][Td]
__device__ __half g_q16[BTd*Hd];
__device__ __half g_k16[BTd*Hd];
__device__ __half g_sc16[(size_t)Bd*Td*Td];
__device__ __half g_y16[BTd*Hd];
__device__ __half g_h2_16[BTd*Hd];
__device__ __half g_gbuf16[(size_t)8*BTd*Fd];  // 7 routed + 1 shared slices
__device__ float  g_h2[BTd*Hd];
__device__ float  g_x1[BTd*Hd];
__device__ float  g_shb[BTd*Hd];
__device__ float  g_r0[BTd*Hd];
__device__ float  g_r1[BTd*Hd];
__device__ int    g_cnt[Ed];
__device__ int    g_gidx[Ed*BTd];
__device__ float  g_gwt[Ed*BTd];
__device__ int    g_gslot[Ed*BTd];

// ---------------- fp16 helpers ----------------
__device__ __forceinline__ unsigned f2h2(float lo, float hi) {
    __half2 h = __floats2half2_rn(lo, hi);
    return *(unsigned*)&h;
}

// ---------------- weight conversion ----------------
struct CVT {
    const float* src[12];
    __half* dst[12];
    int n[12];
};

__global__ void cvt_kernel(CVT cv) {
    int seg = blockIdx.y;
    int idx = blockIdx.x * 256 + threadIdx.x;
    int n8 = cv.n[seg] >> 3;
    if (idx >= n8) return;
    const float4* s = (const float4*)cv.src[seg];
    float4 f1 = s[2*idx], f2 = s[2*idx+1];
    uint4 o;
    o.x = f2h2(f1.x, f1.y); o.y = f2h2(f1.z, f1.w);
    o.z = f2h2(f2.x, f2.y); o.w = f2h2(f2.z, f2.w);
    ((uint4*)cv.dst[seg])[idx] = o;
}

// ---------------- block reduce ----------------
template<bool DOMAX>
__device__ __forceinline__ float blockReduce(float v) {
    __shared__ float sh[8];
    __shared__ float res;
    int lane = threadIdx.x & 31, w = threadIdx.x >> 5;
    #pragma unroll
    for (int o = 16; o; o >>= 1) {
        float t = __shfl_xor_sync(0xffffffffu, v, o);
        v = DOMAX ? fmaxf(v, t) : v + t;
    }
    if (lane == 0) sh[w] = v;
    __syncthreads();
    if (w == 0) {
        v = (lane < (int)(blockDim.x >> 5)) ? sh[lane] : (DOMAX ? -3.4e38f : 0.f);
        #pragma unroll
        for (int o = 4; o; o >>= 1) {
            float t = __shfl_xor_sync(0xffffffffu, v, o);
            v = DOMAX ? fmaxf(v, t) : v + t;
        }
        if (lane == 0) res = v;
    }
    __syncthreads();
    return res;
}

// ---------------- layernorm (fp16 out, optional fp32 copy) ----------------
__global__ void ln_kernel(const float* __restrict__ x, const float* __restrict__ w,
                          __half* __restrict__ o16, float* __restrict__ o32) {
    int row = blockIdx.x;
    const float* xr = x + (size_t)row * Hd;
    int t = threadIdx.x;
    float v[4];
    float s = 0.f;
    #pragma unroll
    for (int i = 0; i < 4; i++) { v[i] = xr[t + 256*i]; s += v[i]; }
    s = blockReduce<false>(s);
    float mu = s * (1.f / Hd);
    float q = 0.f;
    #pragma unroll
    for (int i = 0; i < 4; i++) { float d = v[i] - mu; q += d * d; }
    q = blockReduce<false>(q);
    float rs = rsqrtf(q * (1.f / Hd) + 1e-5f);
    #pragma unroll
    for (int i = 0; i < 4; i++) {
        float val = (v[i] - mu) * rs * w[t + 256*i];
        o16[(size_t)row*Hd + t + 256*i] = __float2half_rn(val);
        if (o32) o32[(size_t)row*Hd + t + 256*i] = val;
    }
}

// ---------------- rope (fp16 in/out) ----------------
__global__ void rope_kernel(__half* __restrict__ q, __half* __restrict__ k) {
    int row = blockIdx.x;
    int t = row % Td;
    size_t base = (size_t)row * Hd;
    #pragma unroll
    for (int it = 0; it < 2; it++) {
        int p = threadIdx.x + 256 * it;
        double invf = exp(-(double)(2 * p) / 1024.0 * 9.210340371976184);
        float f = (float)t * (float)invf;
        float c = cosf(f), s = sinf(f);
        float q1 = __half2float(q[base + p]), q2 = __half2float(q[base + p + 512]);
        q[base + p]       = __float2half_rn(q1 * c - q2 * s);
        q[base + p + 512] = __float2half_rn(q2 * c + q1 * s);
        float k1 = __half2float(k[base + p]), k2 = __half2float(k[base + p + 512]);
        k[base + p]       = __float2half_rn(k1 * c - k2 * s);
        k[base + p + 512] = __float2half_rn(k2 * c + k1 * s);
    }
}

// ---------------- softmax (causal, fp16, single pass) ----------------
__global__ void softmax_kernel(__half* __restrict__ sc) {
    int b = blockIdx.y, i = blockIdx.x;
    __half* row = sc + ((size_t)b * Td + i) * Td;
    int t = threadIdx.x;
    int n = i + 1;
    uint4 u = *(const uint4*)(row + t*8);
    __half2* hp = (__half2*)&u;
    float v[8];
    #pragma unroll
    for (int j = 0; j < 4; j++) {
        v[2*j]   = __low2float(hp[j]);
        v[2*j+1] = __high2float(hp[j]);
    }
    float mx = -3.4e38f;
    #pragma unroll
    for (int j = 0; j < 8; j++)
        if (t*8 + j < n) mx = fmaxf(mx, v[j]);
    mx = blockReduce<true>(mx);
    float s = 0.f;
    #pragma unroll
    for (int j = 0; j < 8; j++) {
        float e = (t*8 + j < n) ? expf(v[j] - mx) : 0.f;
        v[j] = e; s += e;
    }
    s = blockReduce<false>(s);
    float inv = 1.f / s;
    #pragma unroll
    for (int j = 0; j < 4; j++)
        hp[j] = __floats2half2_rn(v[2*j]*inv, v[2*j+1]*inv);
    *(uint4*)(row + t*8) = u;
}

// ---------------- router + top2 gather lists ----------------
__global__ void zero_cnt_kernel() {
    if (threadIdx.x < Ed) g_cnt[threadIdx.x] = 0;
}

__global__ void router_kernel(const float* __restrict__ h2, const float* __restrict__ rw,
                              const float* __restrict__ rb) {
    int m = blockIdx.x;
    int w = threadIdx.x >> 5, lane = threadIdx.x & 31;
    __shared__ float probs[Ed];
    if (w < Ed) {
        const float* hv = h2 + (size_t)m * Hd;
        const float* wv = rw + (size_t)w * Hd;
        float s = 0.f;
        for (int j = lane; j < Hd; j += 32) s += hv[j] * wv[j];
        #pragma unroll
        for (int o = 16; o; o >>= 1) s += __shfl_xor_sync(0xffffffffu, s, o);
        if (lane == 0) probs[w] = 1.f / (1.f + expf(-(s + rb[w])));
    }
    __syncthreads();
    if (threadIdx.x == 0) {
        int e0 = 0; float p0 = probs[0];
        for (int e = 1; e < Ed; e++) if (probs[e] > p0) { p0 = probs[e]; e0 = e; }
        int e1 = -1; float p1 = -3.4e38f;
        for (int e = 0; e < Ed; e++) if (e != e0 && probs[e] > p1) { p1 = probs[e]; e1 = e; }
        int pos = atomicAdd(&g_cnt[e0], 1);
        g_gidx[e0*BTd + pos] = m; g_gwt[e0*BTd + pos] = p0; g_gslot[e0*BTd + pos] = 0;
        pos = atomicAdd(&g_cnt[e1], 1);
        g_gidx[e1*BTd + pos] = m; g_gwt[e1*BTd + pos] = p1; g_gslot[e1*BTd + pos] = 1;
    }
}

// ---------------- mma / ldmatrix / cp.async ----------------
__device__ __forceinline__ void mma_f16(float* d, const unsigned* a, const unsigned* b) {
    asm volatile(
        "mma.sync.aligned.m16n8k16.row.col.f32.f16.f16.f32 "
        "{%0,%1,%2,%3}, {%4,%5,%6,%7}, {%8,%9}, {%0,%1,%2,%3};"
        : "+f"(d[0]), "+f"(d[1]), "+f"(d[2]), "+f"(d[3])
        : "r"(a[0]), "r"(a[1]), "r"(a[2]), "r"(a[3]), "r"(b[0]), "r"(b[1]));
}

__device__ __forceinline__ void ldsm4(unsigned* r, unsigned addr) {
    asm volatile("ldmatrix.sync.aligned.m8n8.x4.shared.b16 {%0,%1,%2,%3}, [%4];"
        : "=r"(r[0]), "=r"(r[1]), "=r"(r[2]), "=r"(r[3]) : "r"(addr));
}

__device__ __forceinline__ void cpa16(unsigned dst, const void* src, unsigned sz) {
    asm volatile("cp.async.cg.shared.global [%0], [%1], 16, %2;"
        :: "r"(dst), "l"(src), "r"(sz) : "memory");
}

__device__ __forceinline__ unsigned smem_u32(const void* p) {
    unsigned a;
    asm("{ .reg .u64 t; cvta.to.shared.u64 t, %1; cvt.u32.u64 %0, t; }" : "=r"(a) : "l"(p));
    return a;
}

// crosswise swizzle: 16B chunk (row, c) -> byte offset within a tile buffer
__device__ __forceinline__ unsigned swz(int row, int c) {
    int line = row >> 1;
    return (unsigned)(line*128 + (((((row & 1) << 2) | c) ^ (line & 7)) << 4));
}

// per-z dims + pointer tables for heterogeneous batched launches
struct GA {
    const void* A[8];
    const void* B[8];
    void*       C[8];
    const void* aux[8];
    float* r0; float* r1;
    int M[8], N[8], K[8], lda[8], ldb[8], ldc[8];
    int ngather;   // z < ngather -> A rows gathered via gidx, Meff = gcnt[z]
    const int* gcnt; const int* gidx; const float* gwt; const int* gslot;
};

// ---------------- fp16 mma GEMM, 128x128 tile, 256 thr, 2 CTAs/SM --------
// C = A @ B^T, per-z shapes. 8 warps, 4x2 grid, warp tile 32x64.
// cp.async 4-stage pipeline; two independent CTAs per SM interleave so the
// tensor pipe stays fed across each CTA's barrier/wait.
// MODE 0: C=v  1: silu  2: C=v*aux  3: C=v+aux(f32)
//      4: scatter w*v to (r0|r1)[gidx] (f32)   5: C=v/32, causal tile skip
// KLIM: clamp K to bm+128 (causal PV)
template<int MODE, bool OHALF, bool KLIM>
__global__ void __launch_bounds__(256, 2) gemm9(GA ga) {
    const int z = blockIdx.z;
    const int bm = blockIdx.y * 128;
    const int bn = blockIdx.x * 128;
    const int Mz = ga.M[z], Nz = ga.N[z];
    if (bn >= Nz || bm >= Mz) return;
    if (MODE == 5 && bn > bm + 127) return;

    const bool gath = z < ga.ngather;
    int Meff = Mz;
    const int* gidx = nullptr; const float* gwt = nullptr; const int* gslot = nullptr;
    if (gath || MODE == 4) {
        Meff = ga.gcnt[z];
        gidx = ga.gidx + z * BTd;
        gwt  = ga.gwt  + z * BTd;
        gslot= ga.gslot+ z * BTd;
    }
    if (bm >= Meff) return;

    const __half* __restrict__ A  = (const __half*)ga.A[z];
    const __half* __restrict__ Bm = (const __half*)ga.B[z];
    int K = ga.K[z];
    if (KLIM) K = (bm + 128 < K) ? bm + 128 : K;
    const int lda = ga.lda[z], ldb = ga.ldb[z], ldc = ga.ldc[z];

    extern __shared__ __align__(16) unsigned char smraw[];
    const unsigned sbase = smem_u32(smraw);

    const int tid = threadIdx.x;
    const int lane = tid & 31, wid = tid >> 5;
    const int wm = wid & 3, wn = wid >> 2;      // 4 x 2 warps, 32x64 each
    const int gid = lane >> 2, tig = lane & 3;

    // ---- cp.async source setup (64 quads; 2 A rows + 2 B rows each) ----
    const int tid4 = tid >> 2, cA = tid & 3;
    const __half* srcA[2]; unsigned szA[2]; unsigned dA[2];
    #pragma unroll
    for (int j = 0; j < 2; j++) {
        int lr = tid4 + 64*j;
        int gr = bm + lr;
        bool val = gr < Meff;
        int sr = val ? (gath ? gidx[gr] : gr) : 0;
        srcA[j] = A + (size_t)sr * lda + cA * 8;
        szA[j] = val ? 16u : 0u;
        dA[j] = swz(lr, cA);
    }
    const __half* srcB[2]; unsigned dB[2]; unsigned szB[2];
    #pragma unroll
    for (int j = 0; j < 2; j++) {
        int lr = tid4 + 64*j;
        int gr = bn + lr;
        bool val = gr < Nz;
        srcB[j] = Bm + (size_t)(val ? gr : 0) * ldb + cA * 8;
        szB[j] = val ? 16u : 0u;
        dB[j] = swz(lr, cA);
    }

    // ---- ldmatrix per-lane offsets (stage-relative) ----
    unsigned offA[2][2], offB[4][2];
    #pragma unroll
    for (int mt = 0; mt < 2; mt++) {
        int row = wm*32 + mt*16 + ((lane >> 3) & 1)*8 + (lane & 7);
        #pragma unroll
        for (int g = 0; g < 2; g++)
            offA[mt][g] = swz(row, g*2 + ((lane >> 4) & 1));
    }
    #pragma unroll
    for (int q = 0; q < 4; q++) {
        int row = wn*64 + q*16 + ((lane >> 4) & 1)*8 + (lane & 7);
        #pragma unroll
        for (int g = 0; g < 2; g++)
            offB[q][g] = swz(row, g*2 + ((lane >> 3) & 1));
    }

    float acc[2][8][4];
    #pragma unroll
    for (int i = 0; i < 2; i++)
        #pragma unroll
        for (int j = 0; j < 8; j++)
            #pragma unroll
            for (int l = 0; l < 4; l++) acc[i][j][l] = 0.f;

    auto issue = [&](int it) {
        int s = it & 3;
        unsigned ab = sbase + s*16384;
        unsigned bb = ab + 8192;
        size_t ko = (size_t)it * 32;
        cpa16(ab + dA[0], srcA[0] + ko, szA[0]);
        cpa16(ab + dA[1], srcA[1] + ko, szA[1]);
        cpa16(bb + dB[0], srcB[0] + ko, szB[0]);
        cpa16(bb + dB[1], srcB[1] + ko, szB[1]);
    };

    const int NT = K / 32;
    issue(0); asm volatile("cp.async.commit_group;" ::: "memory");
    issue(1); asm volatile("cp.async.commit_group;" ::: "memory");
    issue(2); asm volatile("cp.async.commit_group;" ::: "memory");

    for (int it = 0; it < NT; it++) {
        asm volatile("cp.async.wait_group 2;" ::: "memory");
        __syncthreads();
        if (it + 3 < NT) issue(it + 3);
        asm volatile("cp.async.commit_group;" ::: "memory");

        unsigned ab = sbase + (it & 3)*16384;
        unsigned bb = ab + 8192;
        #pragma unroll
        for (int g = 0; g < 2; g++) {
            unsigned a[2][4], b[4][4];
            #pragma unroll
            for (int mt = 0; mt < 2; mt++) ldsm4(a[mt], ab + offA[mt][g]);
            #pragma unroll
            for (int q = 0; q < 4; q++) ldsm4(b[q], bb + offB[q][g]);
            #pragma unroll
            for (int mt = 0; mt < 2; mt++)
                #pragma unroll
                for (int nt = 0; nt < 8; nt++)
                    mma_f16(acc[mt][nt], a[mt], &b[nt >> 1][(nt & 1)*2]);
        }
    }

    // ---- epilogue ----
    #pragma unroll
    for (int mt = 0; mt < 2; mt++) {
        #pragma unroll
        for (int i2 = 0; i2 < 2; i2++) {
            int gm = bm + wm*32 + mt*16 + gid + i2*8;
            if (gm >= Meff) continue;
            int trow = 0; float wgt = 0.f; float* Ct = nullptr;
            if (MODE == 4) { trow = gidx[gm]; wgt = gwt[gm]; Ct = gslot[gm] ? ga.r1 : ga.r0; }
            #pragma unroll
            for (int nt = 0; nt < 8; nt++) {
                int gn = bn + wn*64 + nt*8 + tig*2;
                if (gn >= Nz) continue;
                float v0 = acc[mt][nt][i2*2 + 0];
                float v1 = acc[mt][nt][i2*2 + 1];
                size_t o = (size_t)gm * ldc + gn;
                if (MODE == 1) {
                    v0 = v0 / (1.f + expf(-v0));
                    v1 = v1 / (1.f + expf(-v1));
                } else if (MODE == 2) {
                    __half2 a2 = *(const __half2*)((const __half*)ga.aux[z] + o);
                    v0 *= __low2float(a2); v1 *= __high2float(a2);
                } else if (MODE == 3) {
                    float2 a2 = *(const float2*)((const float*)ga.aux[z] + o);
                    v0 += a2.x; v1 += a2.y;
                } else if (MODE == 5) {
                    v0 *= 0.03125f; v1 *= 0.03125f;
                }
                if (MODE == 4) {
                    float2 w2; w2.x = wgt*v0; w2.y = wgt*v1;
                    *(float2*)(Ct + (size_t)trow * ldc + gn) = w2;
                } else if (OHALF) {
                    *(__half2*)((__half*)ga.C[z] + o) = __floats2half2_rn(v0, v1);
                } else {
                    float2 w2; w2.x = v0; w2.y = v1;
                    *(float2*)((float*)ga.C[z] + o) = w2;
                }
            }
        }
    }
}

// ---------------- final add ----------------
__global__ void final_add_kernel(const float* __restrict__ a, const float* __restrict__ b,
                                 const float* __restrict__ c, const float* __restrict__ d,
                                 float* __restrict__ out) {
    size_t i = (size_t)blockIdx.x * blockDim.x + threadIdx.x;
    out[i] = a[i] + b[i] + c[i] + d[i];
}

// ---------------- launch ----------------
extern "C" void kernel_launch(void* const* d_in, const int* in_sizes, int n_in,
                              void* d_out, int out_size) {
    (void)in_sizes; (void)n_in; (void)out_size;
    const float* x         = (const float*)d_in[0];
    const float* ln1w      = (const float*)d_in[1];
    const float* ln2w      = (const float*)d_in[2];
    const float* kv_proj_d = (const float*)d_in[3];
    const float* q_proj_d  = (const float*)d_in[4];
    const float* v_proj_u  = (const float*)d_in[7];
    const float* rope_k    = (const float*)d_in[8];
    const float* rope_q    = (const float*)d_in[9];
    const float* o_proj    = (const float*)d_in[10];
    const float* router_w  = (const float*)d_in[11];
    const float* router_b  = (const float*)d_in[12];
    const float* sh_gate   = (const float*)d_in[13];
    const float* sh_up     = (const float*)d_in[14];
    const float* sh_down   = (const float*)d_in[15];
    const float* ex_gate   = (const float*)d_in[16];
    const float* ex_up     = (const float*)d_in[17];
    const float* ex_down   = (const float*)d_in[18];
    float* out = (float*)d_out;

    __half *w16,*h16,*qlat16,*kvlat16,*vT16,*q16,*k16,*sc16,*y16,*h2_16,*gbuf16;
    float *h2,*x1,*shb,*r0,*r1,*gwt;
    int *cnt,*gidx,*gslot;
    cudaGetSymbolAddress((void**)&w16, g_w16);
    cudaGetSymbolAddress((void**)&h16, g_h16);
    cudaGetSymbolAddress((void**)&qlat16, g_qlat16);
    cudaGetSymbolAddress((void**)&kvlat16, g_kvlat16);
    cudaGetSymbolAddress((void**)&vT16, g_vT16);
    cudaGetSymbolAddress((void**)&q16, g_q16);
    cudaGetSymbolAddress((void**)&k16, g_k16);
    cudaGetSymbolAddress((void**)&sc16, g_sc16);
    cudaGetSymbolAddress((void**)&y16, g_y16);
    cudaGetSymbolAddress((void**)&h2_16, g_h2_16);
    cudaGetSymbolAddress((void**)&gbuf16, g_gbuf16);
    cudaGetSymbolAddress((void**)&h2, g_h2);
    cudaGetSymbolAddress((void**)&x1, g_x1);
    cudaGetSymbolAddress((void**)&shb, g_shb);
    cudaGetSymbolAddress((void**)&r0, g_r0);
    cudaGetSymbolAddress((void**)&r1, g_r1);
    cudaGetSymbolAddress((void**)&cnt, g_cnt);
    cudaGetSymbolAddress((void**)&gidx, g_gidx);
    cudaGetSymbolAddress((void**)&gwt, g_gwt);
    cudaGetSymbolAddress((void**)&gslot, g_gslot);

    const size_t ESL = (size_t)BTd * Fd;   // per-expert gbuf16 slice

    // raise dynamic smem limit (idempotent)
    cudaFuncSetAttribute(gemm9<0,true,false>,  cudaFuncAttributeMaxDynamicSharedMemorySize, SMEM_BYTES);
    cudaFuncSetAttribute(gemm9<0,true,true>,   cudaFuncAttributeMaxDynamicSharedMemorySize, SMEM_BYTES);
    cudaFuncSetAttribute(gemm9<5,true,false>,  cudaFuncAttributeMaxDynamicSharedMemorySize, SMEM_BYTES);
    cudaFuncSetAttribute(gemm9<3,false,false>, cudaFuncAttributeMaxDynamicSharedMemorySize, SMEM_BYTES);
    cudaFuncSetAttribute(gemm9<1,true,false>,  cudaFuncAttributeMaxDynamicSharedMemorySize, SMEM_BYTES);
    cudaFuncSetAttribute(gemm9<2,true,false>,  cudaFuncAttributeMaxDynamicSharedMemorySize, SMEM_BYTES);
    cudaFuncSetAttribute(gemm9<0,false,false>, cudaFuncAttributeMaxDynamicSharedMemorySize, SMEM_BYTES);
    cudaFuncSetAttribute(gemm9<4,false,false>, cudaFuncAttributeMaxDynamicSharedMemorySize, SMEM_BYTES);

    // ---- weight conversion (fp32 -> fp16 pool) ----
    {
        CVT cv;
        cv.src[0] = q_proj_d;  cv.dst[0] = w16 + W_QPD; cv.n[0] = Ld*Hd;
        cv.src[1] = kv_proj_d; cv.dst[1] = w16 + W_KVD; cv.n[1] = Ld*Hd;
        cv.src[2] = v_proj_u;  cv.dst[2] = w16 + W_VPU; cv.n[2] = Hd*Ld;
        cv.src[3] = rope_q;    cv.dst[3] = w16 + W_RQ;  cv.n[3] = Hd*Ld;
        cv.src[4] = rope_k;    cv.dst[4] = w16 + W_RK;  cv.n[4] = Hd*Hd;
        cv.src[5] = o_proj;    cv.dst[5] = w16 + W_OPJ; cv.n[5] = Hd*Hd;
        cv.src[6] = sh_gate;   cv.dst[6] = w16 + W_SHG; cv.n[6] = Fd*Hd;
        cv.src[7] = sh_up;     cv.dst[7] = w16 + W_SHU; cv.n[7] = Fd*Hd;
        cv.src[8] = sh_down;   cv.dst[8] = w16 + W_SHD; cv.n[8] = Hd*Fd;
        cv.src[9] = ex_gate;   cv.dst[9] = w16 + W_EXG; cv.n[9] = Ed*Fd*Hd;
        cv.src[10]= ex_up;     cv.dst[10]= w16 + W_EXU; cv.n[10]= Ed*Fd*Hd;
        cv.src[11]= ex_down;   cv.dst[11]= w16 + W_EXD; cv.n[11]= Ed*Hd*Fd;
        int mx = Ed*Fd*Hd/8;
        cvt_kernel<<<dim3((mx + 255)/256, 12), 256>>>(cv);
    }

    zero_cnt_kernel<<<1, 32>>>();
    ln_kernel<<<BTd, 256>>>(x, ln1w, h16, nullptr);

    // merged: qlat (z0), kvlat (z1), k_r (z2)
    {
        GA ga = {};
        ga.A[0] = h16; ga.A[1] = h16; ga.A[2] = h16;
        ga.B[0] = w16 + W_QPD; ga.B[1] = w16 + W_KVD; ga.B[2] = w16 + W_RK;
        ga.C[0] = qlat16; ga.C[1] = kvlat16; ga.C[2] = k16;
        for (int zz = 0; zz < 3; zz++) {
            ga.M[zz] = BTd; ga.K[zz] = Hd; ga.lda[zz] = Hd; ga.ldb[zz] = Hd;
        }
        ga.N[0] = Ld; ga.N[1] = Ld; ga.N[2] = Hd;
        ga.ldc[0] = Ld; ga.ldc[1] = Ld; ga.ldc[2] = Hd;
        gemm9<0,true,false><<<dim3(Hd/128, BTd/128, 3), 256, SMEM_BYTES>>>(ga);
    }
    // merged: vT b0 (z0), vT b1 (z1), q_r (z2)
    {
        GA ga = {};
        for (int b = 0; b < Bd; b++) {
            ga.A[b] = w16 + W_VPU;
            ga.B[b] = kvlat16 + (size_t)b*Td*Ld;
            ga.C[b] = vT16 + (size_t)b*Hd*Td;
            ga.M[b] = Hd; ga.N[b] = Td; ga.K[b] = Ld;
            ga.lda[b] = Ld; ga.ldb[b] = Ld; ga.ldc[b] = Td;
        }
        ga.A[2] = qlat16; ga.B[2] = w16 + W_RQ; ga.C[2] = q16;
        ga.M[2] = BTd; ga.N[2] = Hd; ga.K[2] = Ld;
        ga.lda[2] = Ld; ga.ldb[2] = Ld; ga.ldc[2] = Hd;
        gemm9<0,true,false><<<dim3(Td/128, BTd/128, 3), 256, SMEM_BYTES>>>(ga);
    }

    rope_kernel<<<BTd, 256>>>(q16, k16);

    // scores (z=2, causal tile skip)
    {
        GA ga = {};
        for (int b = 0; b < Bd; b++) {
            ga.A[b] = q16 + (size_t)b*Td*Hd;
            ga.B[b] = k16 + (size_t)b*Td*Hd;
            ga.C[b] = sc16 + (size_t)b*Td*Td;
            ga.M[b] = Td; ga.N[b] = Td; ga.K[b] = Hd;
            ga.lda[b] = Hd; ga.ldb[b] = Hd; ga.ldc[b] = Td;
        }
        gemm9<5,true,false><<<dim3(Td/128, Td/128, Bd), 256, SMEM_BYTES>>>(ga);
    }
    softmax_kernel<<<dim3(Td, Bd), 256>>>(sc16);
    // PV (z=2): y[b] = attn[b] @ vT[b]^T, causal K-limit
    {
        GA ga = {};
        for (int b = 0; b < Bd; b++) {
            ga.A[b] = sc16 + (size_t)b*Td*Td;
            ga.B[b] = vT16 + (size_t)b*Hd*Td;
            ga.C[b] = y16 + (size_t)b*Td*Hd;
            ga.M[b] = Td; ga.N[b] = Hd; ga.K[b] = Td;
            ga.lda[b] = Td; ga.ldb[b] = Td; ga.ldc[b] = Hd;
        }
        gemm9<0,true,true><<<dim3(Hd/128, Td/128, Bd), 256, SMEM_BYTES>>>(ga);
    }
    // x1 = x + y @ o_proj.T  (fp32 out)
    {
        GA ga = {};
        ga.A[0] = y16; ga.B[0] = w16 + W_OPJ; ga.C[0] = x1; ga.aux[0] = x;
        ga.M[0] = BTd; ga.N[0] = Hd; ga.K[0] = Hd;
        ga.lda[0] = Hd; ga.ldb[0] = Hd; ga.ldc[0] = Hd;
        gemm9<3,false,false><<<dim3(Hd/128, BTd/128, 1), 256, SMEM_BYTES>>>(ga);
    }

    // ---- MoE ----
    ln_kernel<<<BTd, 256>>>(x1, ln2w, h2_16, h2);
    router_kernel<<<BTd, 256>>>(h2, router_w, router_b);

    __half* shg = gbuf16 + (size_t)7 * ESL;
    // merged gate (silu): z0..6 routed experts (gathered), z7 shared (dense)
    {
        GA ga = {};
        for (int e = 0; e < Ed; e++) {
            ga.A[e] = h2_16;
            ga.B[e] = w16 + W_EXG + (size_t)e * Fd * Hd;
            ga.C[e] = gbuf16 + (size_t)e * ESL;
        }
        ga.A[7] = h2_16; ga.B[7] = w16 + W_SHG; ga.C[7] = shg;
        for (int zz = 0; zz < 8; zz++) {
            ga.M[zz] = BTd; ga.N[zz] = Fd; ga.K[zz] = Hd;
            ga.lda[zz] = Hd; ga.ldb[zz] = Hd; ga.ldc[zz] = Fd;
        }
        ga.ngather = Ed;
        ga.gcnt = cnt; ga.gidx = gidx; ga.gwt = gwt; ga.gslot = gslot;
        gemm9<1,true,false><<<dim3(Fd/128, BTd/128, 8), 256, SMEM_BYTES>>>(ga);
    }
    // merged up (in-place multiply): z0..6 routed (gathered), z7 shared
    {
        GA ga = {};
        for (int e = 0; e < Ed; e++) {
            ga.A[e] = h2_16;
            ga.B[e] = w16 + W_EXU + (size_t)e * Fd * Hd;
            ga.C[e] = gbuf16 + (size_t)e * ESL;
            ga.aux[e] = gbuf16 + (size_t)e * ESL;
        }
        ga.A[7] = h2_16; ga.B[7] = w16 + W_SHU; ga.C[7] = shg; ga.aux[7] = shg;
        for (int zz = 0; zz < 8; zz++) {
            ga.M[zz] = BTd; ga.N[zz] = Fd; ga.K[zz] = Hd;
            ga.lda[zz] = Hd; ga.ldb[zz] = Hd; ga.ldc[zz] = Fd;
        }
        ga.ngather = Ed;
        ga.gcnt = cnt; ga.gidx = gidx; ga.gwt = gwt; ga.gslot = gslot;
        gemm9<2,true,false><<<dim3(Fd/128, BTd/128, 8), 256, SMEM_BYTES>>>(ga);
    }
    // shared down (fp32 out)
    {
        GA ga = {};
        ga.A[0] = shg; ga.B[0] = w16 + W_SHD; ga.C[0] = shb;
        ga.M[0] = BTd; ga.N[0] = Hd; ga.K[0] = Fd;
        ga.lda[0] = Fd; ga.ldb[0] = Fd; ga.ldc[0] = Hd;
        gemm9<0,false,false><<<dim3(Hd/128, BTd/128, 1), 256, SMEM_BYTES>>>(ga);
    }
    // expert down (scatter), z0..6
    {
        GA ga = {};
        for (int e = 0; e < Ed; e++) {
            ga.A[e] = gbuf16 + (size_t)e * ESL;
            ga.B[e] = w16 + W_EXD + (size_t)e * Hd * Fd;
            ga.M[e] = BTd; ga.N[e] = Hd; ga.K[e] = Fd;
            ga.lda[e] = Fd; ga.ldb[e] = Fd; ga.ldc[e] = Hd;
        }
        ga.r0 = r0; ga.r1 = r1;
        ga.ngather = 0;
        ga.gcnt = cnt; ga.gidx = gidx; ga.gwt = gwt; ga.gslot = gslot;
        gemm9<4,false,false><<<dim3(Hd/128, BTd/128, Ed), 256, SMEM_BYTES>>>(ga);
    }

    final_add_kernel<<<(BTd * Hd) / 256, 256>>>(x1, shb, r0, r1, out);
}